// round 13
// baseline (speedup 1.0000x reference)
#include <cuda_runtime.h>
#include <cuda_bf16.h>
#include <cstdint>
#include <cstddef>

// Problem constants
#define E_    8
#define H_    2048
#define I_    2816
#define T_    512
#define TWO_I 5632
#define NB1   44   // (2I)/128 n-blocks for w13_scale
#define KB1   16   // H/128 k-blocks for w13_scale
#define NB2   16   // H/128 n-blocks for w2_scale
#define KB2   22   // I/128 k-blocks for w2_scale

// ---------------- device scratch (no runtime allocation allowed) -------------
__device__ __nv_bfloat16 g_xh[T_ * H_];
__device__ __nv_bfloat16 g_xl[T_ * H_];
__device__ float         g_h[(size_t)E_ * T_ * TWO_I];   // GEMM1 output (fp32)
__device__ __nv_bfloat16 g_ah[(size_t)E_ * T_ * I_];     // act hi
__device__ __nv_bfloat16 g_al[(size_t)E_ * T_ * I_];     // act lo
__device__ int           g_tok[E_ * T_];
__device__ float         g_coef[E_ * T_];
__device__ int           g_cnt[E_];

// ---------------- helpers ----------------------------------------------------
__device__ __forceinline__ unsigned pk2(float a, float b) {
    __nv_bfloat162 t = __floats2bfloat162_rn(a, b);  // a -> low, b -> high
    return *reinterpret_cast<unsigned*>(&t);
}

__device__ __forceinline__ void ldsm4(unsigned& r0, unsigned& r1, unsigned& r2,
                                      unsigned& r3, const void* p) {
    unsigned a = (unsigned)__cvta_generic_to_shared(p);
    asm volatile("ldmatrix.sync.aligned.m8n8.x4.shared.b16 {%0,%1,%2,%3}, [%4];\n"
                 : "=r"(r0), "=r"(r1), "=r"(r2), "=r"(r3)
                 : "r"(a));
}

__device__ __forceinline__ void mma16816(float* c, unsigned a0, unsigned a1,
                                         unsigned a2, unsigned a3,
                                         unsigned b0, unsigned b1) {
    asm volatile(
        "mma.sync.aligned.m16n8k16.row.col.f32.bf16.bf16.f32 "
        "{%0,%1,%2,%3}, {%4,%5,%6,%7}, {%8,%9}, {%0,%1,%2,%3};\n"
        : "+f"(c[0]), "+f"(c[1]), "+f"(c[2]), "+f"(c[3])
        : "r"(a0), "r"(a1), "r"(a2), "r"(a3), "r"(b0), "r"(b1));
}

// Smem swizzle: rows are 64 bf16 (128B) wide; 8 chunks of 8 bf16 (16B).
// chunk' = chunk ^ (row&7) -> conflict-free ldmatrix across 8 rows.
__device__ __forceinline__ int swz(int row, int chunk) {
    return row * 64 + ((chunk ^ (row & 7)) << 3);
}

// ---------------- prep: split x into bf16 hi/lo, zero the output -------------
__global__ void k_prep(const float* __restrict__ x, float* __restrict__ out) {
    int i = blockIdx.x * 256 + threadIdx.x;   // grid sized exactly T_*H_/256
    float v = x[i];
    __nv_bfloat16 h = __float2bfloat16(v);
    g_xh[i] = h;
    g_xl[i] = __float2bfloat16(v - __bfloat162float(h));
    out[i] = 0.f;
}

// ---------------- routing: per-expert token list + coef ---------------------
// topk_ids may be int64 or int32 depending on jax x64 config; detect at runtime.
__global__ void k_route(const void* __restrict__ ids_raw,
                        const float* __restrict__ w) {
    __shared__ int s64;
    int tid = threadIdx.x;
    if (tid == 0) s64 = 1;
    __syncthreads();
    const long long* p64 = (const long long*)ids_raw;
    const int*       p32 = (const int*)ids_raw;
    // First 512 int64 reads = 4096 bytes, in-bounds under both dtypes.
    for (int i = tid; i < 512; i += 256) {
        long long v = p64[i];
        if (v < 0 || v >= E_) s64 = 0;
    }
    __syncthreads();
    int is64 = s64;

    int warp = tid >> 5, lane = tid & 31;
    int e = warp;             // 8 warps, one expert each
    int c = 0;
    for (int t0 = 0; t0 < T_; t0 += 32) {
        int t = t0 + lane;
        int id0, id1;
        if (is64) { id0 = (int)p64[2 * t]; id1 = (int)p64[2 * t + 1]; }
        else      { id0 = p32[2 * t];      id1 = p32[2 * t + 1]; }
        float cf = 0.f;
        bool hit = false;
        if (id0 == e) { cf += w[2 * t];     hit = true; }
        if (id1 == e) { cf += w[2 * t + 1]; hit = true; }
        unsigned m = __ballot_sync(0xffffffffu, hit);
        if (hit) {
            int pos = c + __popc(m & ((1u << lane) - 1u));
            g_tok[e * T_ + pos]  = t;
            g_coef[e * T_ + pos] = cf;
        }
        c += __popc(m);
    }
    if (lane == 0) g_cnt[e] = c;
}

// ---------------- GEMM1: h[slot, n] = sum_k x[tok,k]*W13[e,n,k]*scale -------
// Tile: BM=64 (gathered token rows) x BN=128 x KC=64, 8 warps (4x2),
// warp tile 16x64. A split hi/lo (2 mma passes), scale applied on fp32
// accumulator every 2 k-chunks (= one 128 scale block).
__global__ __launch_bounds__(256, 2)
void k_gemm1(const float* __restrict__ w13, const float* __restrict__ w13s) {
    int nt = blockIdx.x, mt = blockIdx.y, e = blockIdx.z;
    int cnt = g_cnt[e];
    if (mt * 64 >= cnt) return;

    __shared__ __align__(16) __nv_bfloat16 sAh[64 * 64];
    __shared__ __align__(16) __nv_bfloat16 sAl[64 * 64];
    __shared__ __align__(16) __nv_bfloat16 sB[128 * 64];

    int tid = threadIdx.x, lane = tid & 31, warp = tid >> 5;
    int wm = warp >> 1, wn = warp & 1;

    // loader mappings
    int ar = tid >> 2, aq = tid & 3;   // A: 64 rows, 2 chunks/thread
    int br = tid >> 1, bh = tid & 1;   // B: 128 rows, 4 chunks/thread
    int mrow = mt * 64 + ar;
    int tok = (mrow < cnt) ? g_tok[e * T_ + mrow] : -1;
    const __nv_bfloat16* xh_row = g_xh + (size_t)(tok < 0 ? 0 : tok) * H_;
    const __nv_bfloat16* xl_row = g_xl + (size_t)(tok < 0 ? 0 : tok) * H_;
    const float* brow = w13 + ((size_t)e * TWO_I + (size_t)nt * 128 + br) * H_;

    float acc[8][4], tmp[8][4];
#pragma unroll
    for (int s = 0; s < 8; ++s)
#pragma unroll
        for (int j = 0; j < 4; ++j) acc[s][j] = 0.f;

    const int NC = H_ / 64;  // 32
    for (int kc = 0; kc < NC; ++kc) {
        int k0 = kc * 64;
        __syncthreads();
        // --- load A (gathered token rows, already bf16) ---
#pragma unroll
        for (int cc = 0; cc < 2; ++cc) {
            int chunk = aq * 2 + cc;
            uint4 vh = make_uint4(0, 0, 0, 0), vl = make_uint4(0, 0, 0, 0);
            if (tok >= 0) {
                vh = *(const uint4*)(xh_row + k0 + chunk * 8);
                vl = *(const uint4*)(xl_row + k0 + chunk * 8);
            }
            *(uint4*)(sAh + swz(ar, chunk)) = vh;
            *(uint4*)(sAl + swz(ar, chunk)) = vl;
        }
        // --- load B (fp32 -> bf16 exact convert) ---
#pragma unroll
        for (int cc = 0; cc < 4; ++cc) {
            int chunk = bh * 4 + cc;
            const float* p = brow + k0 + chunk * 8;
            float4 f0 = *(const float4*)p;
            float4 f1 = *(const float4*)(p + 4);
            uint4 u;
            u.x = pk2(f0.x, f0.y); u.y = pk2(f0.z, f0.w);
            u.z = pk2(f1.x, f1.y); u.w = pk2(f1.z, f1.w);
            *(uint4*)(sB + swz(br, chunk)) = u;
        }
        __syncthreads();

        if ((kc & 1) == 0) {
#pragma unroll
            for (int s = 0; s < 8; ++s)
#pragma unroll
                for (int j = 0; j < 4; ++j) tmp[s][j] = 0.f;
        }
#pragma unroll
        for (int ks = 0; ks < 4; ++ks) {
            unsigned ah0, ah1, ah2, ah3, al0, al1, al2, al3;
            {
                int row = wm * 16 + (lane & 15);
                int chunk = ks * 2 + (lane >> 4);
                ldsm4(ah0, ah1, ah2, ah3, sAh + swz(row, chunk));
                ldsm4(al0, al1, al2, al3, sAl + swz(row, chunk));
            }
            unsigned bb[16];
#pragma unroll
            for (int g = 0; g < 4; ++g) {
                int row = wn * 64 + g * 16 + (lane & 7) + ((lane >> 4) << 3);
                int chunk = ks * 2 + ((lane >> 3) & 1);
                ldsm4(bb[4 * g], bb[4 * g + 1], bb[4 * g + 2], bb[4 * g + 3],
                      sB + swz(row, chunk));
            }
#pragma unroll
            for (int s = 0; s < 8; ++s) {
                unsigned b0 = bb[4 * (s >> 1) + 2 * (s & 1)];
                unsigned b1 = bb[4 * (s >> 1) + 2 * (s & 1) + 1];
                mma16816(tmp[s], ah0, ah1, ah2, ah3, b0, b1);
                mma16816(tmp[s], al0, al1, al2, al3, b0, b1);
            }
        }
        if (kc & 1) {
            float sc = w13s[((size_t)e * NB1 + nt) * KB1 + (kc >> 1)];
#pragma unroll
            for (int s = 0; s < 8; ++s)
#pragma unroll
                for (int j = 0; j < 4; ++j) acc[s][j] += sc * tmp[s][j];
        }
    }

    // epilogue: write fp32 h tile
    int r0 = lane >> 2, cb = (lane & 3) * 2;
    size_t rowbase = (size_t)(e * T_ + mt * 64 + wm * 16 + r0) * TWO_I;
    int colbase = nt * 128 + wn * 64 + cb;
#pragma unroll
    for (int s = 0; s < 8; ++s) {
        float* p0 = g_h + rowbase + colbase + s * 8;
        *(float2*)p0 = make_float2(acc[s][0], acc[s][1]);
        *(float2*)(p0 + (size_t)8 * TWO_I) = make_float2(acc[s][2], acc[s][3]);
    }
}

// ---------------- SwiGLU + hi/lo split ---------------------------------------
__global__ void k_act() {
    int ic = blockIdx.x, mt = blockIdx.y, e = blockIdx.z;
    if (mt * 64 >= g_cnt[e]) return;
    int tid = threadIdx.x;
    int c4 = (tid & 31) * 4;   // 0..124
    int r0 = tid >> 5;         // 0..7
#pragma unroll
    for (int rr = 0; rr < 64; rr += 8) {
        int row = mt * 64 + rr + r0;
        size_t hbase = (size_t)(e * T_ + row) * TWO_I + (size_t)ic * 128 + c4;
        float4 g = *(const float4*)(g_h + hbase);
        float4 u = *(const float4*)(g_h + hbase + I_);
        float a0 = u.x * (g.x / (1.f + __expf(-g.x)));
        float a1 = u.y * (g.y / (1.f + __expf(-g.y)));
        float a2 = u.z * (g.z / (1.f + __expf(-g.z)));
        float a3 = u.w * (g.w / (1.f + __expf(-g.w)));
        uint2 uh;
        uh.x = pk2(a0, a1);
        uh.y = pk2(a2, a3);
        __nv_bfloat162 h01 = *reinterpret_cast<__nv_bfloat162*>(&uh.x);
        __nv_bfloat162 h23 = *reinterpret_cast<__nv_bfloat162*>(&uh.y);
        float l0 = a0 - __bfloat162float(h01.x);
        float l1 = a1 - __bfloat162float(h01.y);
        float l2 = a2 - __bfloat162float(h23.x);
        float l3 = a3 - __bfloat162float(h23.y);
        uint2 ul;
        ul.x = pk2(l0, l1);
        ul.y = pk2(l2, l3);
        size_t abase = (size_t)(e * T_ + row) * I_ + (size_t)ic * 128 + c4;
        *(uint2*)(g_ah + abase) = uh;
        *(uint2*)(g_al + abase) = ul;
    }
}

// ---------------- GEMM2: out[tok] += coef * act @ W2^T (block-scaled) --------
__global__ __launch_bounds__(256, 2)
void k_gemm2(const float* __restrict__ w2, const float* __restrict__ w2s,
             float* __restrict__ out) {
    int nt = blockIdx.x, mt = blockIdx.y, e = blockIdx.z;
    int cnt = g_cnt[e];
    if (mt * 64 >= cnt) return;

    __shared__ __align__(16) __nv_bfloat16 sAh[64 * 64];
    __shared__ __align__(16) __nv_bfloat16 sAl[64 * 64];
    __shared__ __align__(16) __nv_bfloat16 sB[128 * 64];

    int tid = threadIdx.x, lane = tid & 31, warp = tid >> 5;
    int wm = warp >> 1, wn = warp & 1;

    int ar = tid >> 2, aq = tid & 3;
    int br = tid >> 1, bh = tid & 1;
    const __nv_bfloat16* ah_row = g_ah + (size_t)(e * T_ + mt * 64 + ar) * I_;
    const __nv_bfloat16* al_row = g_al + (size_t)(e * T_ + mt * 64 + ar) * I_;
    const float* brow = w2 + ((size_t)e * H_ + (size_t)nt * 128 + br) * I_;

    float acc[8][4], tmp[8][4];
#pragma unroll
    for (int s = 0; s < 8; ++s)
#pragma unroll
        for (int j = 0; j < 4; ++j) acc[s][j] = 0.f;

    const int NC = I_ / 64;  // 44
    for (int kc = 0; kc < NC; ++kc) {
        int k0 = kc * 64;
        __syncthreads();
#pragma unroll
        for (int cc = 0; cc < 2; ++cc) {
            int chunk = aq * 2 + cc;
            uint4 vh = *(const uint4*)(ah_row + k0 + chunk * 8);
            uint4 vl = *(const uint4*)(al_row + k0 + chunk * 8);
            *(uint4*)(sAh + swz(ar, chunk)) = vh;
            *(uint4*)(sAl + swz(ar, chunk)) = vl;
        }
#pragma unroll
        for (int cc = 0; cc < 4; ++cc) {
            int chunk = bh * 4 + cc;
            const float* p = brow + k0 + chunk * 8;
            float4 f0 = *(const float4*)p;
            float4 f1 = *(const float4*)(p + 4);
            uint4 u;
            u.x = pk2(f0.x, f0.y); u.y = pk2(f0.z, f0.w);
            u.z = pk2(f1.x, f1.y); u.w = pk2(f1.z, f1.w);
            *(uint4*)(sB + swz(br, chunk)) = u;
        }
        __syncthreads();

        if ((kc & 1) == 0) {
#pragma unroll
            for (int s = 0; s < 8; ++s)
#pragma unroll
                for (int j = 0; j < 4; ++j) tmp[s][j] = 0.f;
        }
#pragma unroll
        for (int ks = 0; ks < 4; ++ks) {
            unsigned ah0, ah1, ah2, ah3, al0, al1, al2, al3;
            {
                int row = wm * 16 + (lane & 15);
                int chunk = ks * 2 + (lane >> 4);
                ldsm4(ah0, ah1, ah2, ah3, sAh + swz(row, chunk));
                ldsm4(al0, al1, al2, al3, sAl + swz(row, chunk));
            }
            unsigned bb[16];
#pragma unroll
            for (int g = 0; g < 4; ++g) {
                int row = wn * 64 + g * 16 + (lane & 7) + ((lane >> 4) << 3);
                int chunk = ks * 2 + ((lane >> 3) & 1);
                ldsm4(bb[4 * g], bb[4 * g + 1], bb[4 * g + 2], bb[4 * g + 3],
                      sB + swz(row, chunk));
            }
#pragma unroll
            for (int s = 0; s < 8; ++s) {
                unsigned b0 = bb[4 * (s >> 1) + 2 * (s & 1)];
                unsigned b1 = bb[4 * (s >> 1) + 2 * (s & 1) + 1];
                mma16816(tmp[s], ah0, ah1, ah2, ah3, b0, b1);
                mma16816(tmp[s], al0, al1, al2, al3, b0, b1);
            }
        }
        if (kc & 1) {
            float sc = w2s[((size_t)e * NB2 + nt) * KB2 + (kc >> 1)];
#pragma unroll
            for (int s = 0; s < 8; ++s)
#pragma unroll
                for (int j = 0; j < 4; ++j) acc[s][j] += sc * tmp[s][j];
        }
    }

    // epilogue: weighted scatter-add into out (<=2 adds/element -> deterministic)
    int r0 = lane >> 2, cb = (lane & 3) * 2;
    int rloc0 = mt * 64 + wm * 16 + r0;
#pragma unroll
    for (int hrow = 0; hrow < 2; ++hrow) {
        int rl = rloc0 + hrow * 8;
        if (rl < cnt) {
            float cf = g_coef[e * T_ + rl];
            if (cf != 0.f) {
                int tok = g_tok[e * T_ + rl];
                float* op = out + (size_t)tok * H_ + nt * 128 + wn * 64 + cb;
#pragma unroll
                for (int s = 0; s < 8; ++s) {
                    atomicAdd(op + s * 8,     cf * acc[s][2 * hrow + 0]);
                    atomicAdd(op + s * 8 + 1, cf * acc[s][2 * hrow + 1]);
                }
            }
        }
    }
}

// ---------------- launcher ---------------------------------------------------
extern "C" void kernel_launch(void* const* d_in, const int* in_sizes, int n_in,
                              void* d_out, int out_size) {
    const float* x    = (const float*)d_in[0];
    const void*  ids  = d_in[1];
    const float* tw   = (const float*)d_in[2];
    const float* w13  = (const float*)d_in[3];
    const float* w13s = (const float*)d_in[4];
    const float* w2   = (const float*)d_in[5];
    const float* w2s  = (const float*)d_in[6];
    float* out = (float*)d_out;

    k_prep<<<(T_ * H_) / 256, 256>>>(x, out);
    k_route<<<1, 256>>>(ids, tw);
    dim3 g1(NB1, 8, E_);
    k_gemm1<<<g1, 256>>>(w13, w13s);
    dim3 ga(KB2, 8, E_);
    k_act<<<ga, 256>>>();
    dim3 g2(NB2, 8, E_);
    k_gemm2<<<g2, 256>>>(w2, w2s, out);
}

// round 14
// speedup vs baseline: 1.0031x; 1.0031x over previous
#include <cuda_runtime.h>
#include <cuda_bf16.h>
#include <cstdint>
#include <cstddef>

// Problem constants
#define E_    8
#define H_    2048
#define I_    2816
#define T_    512
#define TWO_I 5632
#define NB1   44   // (2I)/128 n-blocks for w13_scale
#define KB1   16   // H/128 k-blocks for w13_scale
#define NB2   16   // H/128 n-blocks for w2_scale
#define KB2   22   // I/128 k-blocks for w2_scale

// ---------------- device scratch (no runtime allocation allowed) -------------
__device__ __nv_bfloat16 g_xh[T_ * H_];
__device__ __nv_bfloat16 g_xl[T_ * H_];
__device__ float         g_h[(size_t)E_ * T_ * TWO_I];   // GEMM1 output (fp32)
__device__ __nv_bfloat16 g_ah[(size_t)E_ * T_ * I_];     // act hi
__device__ __nv_bfloat16 g_al[(size_t)E_ * T_ * I_];     // act lo
__device__ int           g_tok[E_ * T_];
__device__ float         g_coef[E_ * T_];
__device__ int           g_cnt[E_];

// ---------------- helpers ----------------------------------------------------
__device__ __forceinline__ unsigned pk2(float a, float b) {
    __nv_bfloat162 t = __floats2bfloat162_rn(a, b);  // a -> low, b -> high
    return *reinterpret_cast<unsigned*>(&t);
}

__device__ __forceinline__ void ldsm4(unsigned& r0, unsigned& r1, unsigned& r2,
                                      unsigned& r3, const void* p) {
    unsigned a = (unsigned)__cvta_generic_to_shared(p);
    asm volatile("ldmatrix.sync.aligned.m8n8.x4.shared.b16 {%0,%1,%2,%3}, [%4];\n"
                 : "=r"(r0), "=r"(r1), "=r"(r2), "=r"(r3)
                 : "r"(a));
}

__device__ __forceinline__ void mma16816(float* c, unsigned a0, unsigned a1,
                                         unsigned a2, unsigned a3,
                                         unsigned b0, unsigned b1) {
    asm volatile(
        "mma.sync.aligned.m16n8k16.row.col.f32.bf16.bf16.f32 "
        "{%0,%1,%2,%3}, {%4,%5,%6,%7}, {%8,%9}, {%0,%1,%2,%3};\n"
        : "+f"(c[0]), "+f"(c[1]), "+f"(c[2]), "+f"(c[3])
        : "r"(a0), "r"(a1), "r"(a2), "r"(a3), "r"(b0), "r"(b1));
}

// Smem swizzle: rows are 64 bf16 (128B) wide; 8 chunks of 8 bf16 (16B).
// chunk' = chunk ^ (row&7) -> conflict-free ldmatrix across 8 rows.
__device__ __forceinline__ int swz(int row, int chunk) {
    return row * 64 + ((chunk ^ (row & 7)) << 3);
}

// ---------------- prep: split x into bf16 hi/lo, zero the output -------------
__global__ void k_prep(const float* __restrict__ x, float* __restrict__ out) {
    int i = blockIdx.x * 256 + threadIdx.x;   // grid sized exactly T_*H_/256
    float v = x[i];
    __nv_bfloat16 h = __float2bfloat16(v);
    g_xh[i] = h;
    g_xl[i] = __float2bfloat16(v - __bfloat162float(h));
    out[i] = 0.f;
}

// ---------------- routing: per-expert token list + coef ---------------------
// topk_ids may be int64 or int32 depending on jax x64 config; detect at runtime.
__global__ void k_route(const void* __restrict__ ids_raw,
                        const float* __restrict__ w) {
    __shared__ int s64;
    int tid = threadIdx.x;
    if (tid == 0) s64 = 1;
    __syncthreads();
    const long long* p64 = (const long long*)ids_raw;
    const int*       p32 = (const int*)ids_raw;
    // First 512 int64 reads = 4096 bytes, in-bounds under both dtypes.
    for (int i = tid; i < 512; i += 256) {
        long long v = p64[i];
        if (v < 0 || v >= E_) s64 = 0;
    }
    __syncthreads();
    int is64 = s64;

    int warp = tid >> 5, lane = tid & 31;
    int e = warp;             // 8 warps, one expert each
    int c = 0;
    for (int t0 = 0; t0 < T_; t0 += 32) {
        int t = t0 + lane;
        int id0, id1;
        if (is64) { id0 = (int)p64[2 * t]; id1 = (int)p64[2 * t + 1]; }
        else      { id0 = p32[2 * t];      id1 = p32[2 * t + 1]; }
        float cf = 0.f;
        bool hit = false;
        if (id0 == e) { cf += w[2 * t];     hit = true; }
        if (id1 == e) { cf += w[2 * t + 1]; hit = true; }
        unsigned m = __ballot_sync(0xffffffffu, hit);
        if (hit) {
            int pos = c + __popc(m & ((1u << lane) - 1u));
            g_tok[e * T_ + pos]  = t;
            g_coef[e * T_ + pos] = cf;
        }
        c += __popc(m);
    }
    if (lane == 0) g_cnt[e] = c;
}

// ---------------- GEMM1: h[slot, n] = sum_k x[tok,k]*W13[e,n,k]*scale -------
// Tile: BM=64 (gathered token rows) x BN=128 x KC=64, 8 warps (4x2),
// warp tile 16x64. A split hi/lo (2 mma passes), scale applied on fp32
// accumulator every 2 k-chunks (= one 128 scale block).
__global__ __launch_bounds__(256, 2)
void k_gemm1(const float* __restrict__ w13, const float* __restrict__ w13s) {
    int nt = blockIdx.x, mt = blockIdx.y, e = blockIdx.z;
    int cnt = g_cnt[e];
    if (mt * 64 >= cnt) return;

    __shared__ __align__(16) __nv_bfloat16 sAh[64 * 64];
    __shared__ __align__(16) __nv_bfloat16 sAl[64 * 64];
    __shared__ __align__(16) __nv_bfloat16 sB[128 * 64];

    int tid = threadIdx.x, lane = tid & 31, warp = tid >> 5;
    int wm = warp >> 1, wn = warp & 1;

    // loader mappings
    int ar = tid >> 2, aq = tid & 3;   // A: 64 rows, 2 chunks/thread
    int br = tid >> 1, bh = tid & 1;   // B: 128 rows, 4 chunks/thread
    int mrow = mt * 64 + ar;
    int tok = (mrow < cnt) ? g_tok[e * T_ + mrow] : -1;
    const __nv_bfloat16* xh_row = g_xh + (size_t)(tok < 0 ? 0 : tok) * H_;
    const __nv_bfloat16* xl_row = g_xl + (size_t)(tok < 0 ? 0 : tok) * H_;
    const float* brow = w13 + ((size_t)e * TWO_I + (size_t)nt * 128 + br) * H_;

    float acc[8][4], tmp[8][4];
#pragma unroll
    for (int s = 0; s < 8; ++s)
#pragma unroll
        for (int j = 0; j < 4; ++j) acc[s][j] = 0.f;

    const int NC = H_ / 64;  // 32
    for (int kc = 0; kc < NC; ++kc) {
        int k0 = kc * 64;
        __syncthreads();
        // --- load A (gathered token rows, already bf16) ---
#pragma unroll
        for (int cc = 0; cc < 2; ++cc) {
            int chunk = aq * 2 + cc;
            uint4 vh = make_uint4(0, 0, 0, 0), vl = make_uint4(0, 0, 0, 0);
            if (tok >= 0) {
                vh = *(const uint4*)(xh_row + k0 + chunk * 8);
                vl = *(const uint4*)(xl_row + k0 + chunk * 8);
            }
            *(uint4*)(sAh + swz(ar, chunk)) = vh;
            *(uint4*)(sAl + swz(ar, chunk)) = vl;
        }
        // --- load B (fp32 -> bf16 exact convert) ---
#pragma unroll
        for (int cc = 0; cc < 4; ++cc) {
            int chunk = bh * 4 + cc;
            const float* p = brow + k0 + chunk * 8;
            float4 f0 = *(const float4*)p;
            float4 f1 = *(const float4*)(p + 4);
            uint4 u;
            u.x = pk2(f0.x, f0.y); u.y = pk2(f0.z, f0.w);
            u.z = pk2(f1.x, f1.y); u.w = pk2(f1.z, f1.w);
            *(uint4*)(sB + swz(br, chunk)) = u;
        }
        __syncthreads();

        if ((kc & 1) == 0) {
#pragma unroll
            for (int s = 0; s < 8; ++s)
#pragma unroll
                for (int j = 0; j < 4; ++j) tmp[s][j] = 0.f;
        }
#pragma unroll
        for (int ks = 0; ks < 4; ++ks) {
            unsigned ah0, ah1, ah2, ah3, al0, al1, al2, al3;
            {
                int row = wm * 16 + (lane & 15);
                int chunk = ks * 2 + (lane >> 4);
                ldsm4(ah0, ah1, ah2, ah3, sAh + swz(row, chunk));
                ldsm4(al0, al1, al2, al3, sAl + swz(row, chunk));
            }
            unsigned bb[16];
#pragma unroll
            for (int g = 0; g < 4; ++g) {
                int row = wn * 64 + g * 16 + (lane & 7) + ((lane >> 4) << 3);
                int chunk = ks * 2 + ((lane >> 3) & 1);
                ldsm4(bb[4 * g], bb[4 * g + 1], bb[4 * g + 2], bb[4 * g + 3],
                      sB + swz(row, chunk));
            }
#pragma unroll
            for (int s = 0; s < 8; ++s) {
                unsigned b0 = bb[4 * (s >> 1) + 2 * (s & 1)];
                unsigned b1 = bb[4 * (s >> 1) + 2 * (s & 1) + 1];
                mma16816(tmp[s], ah0, ah1, ah2, ah3, b0, b1);
                mma16816(tmp[s], al0, al1, al2, al3, b0, b1);
            }
        }
        if (kc & 1) {
            float sc = w13s[((size_t)e * NB1 + nt) * KB1 + (kc >> 1)];
#pragma unroll
            for (int s = 0; s < 8; ++s)
#pragma unroll
                for (int j = 0; j < 4; ++j) acc[s][j] += sc * tmp[s][j];
        }
    }

    // epilogue: write fp32 h tile
    int r0 = lane >> 2, cb = (lane & 3) * 2;
    size_t rowbase = (size_t)(e * T_ + mt * 64 + wm * 16 + r0) * TWO_I;
    int colbase = nt * 128 + wn * 64 + cb;
#pragma unroll
    for (int s = 0; s < 8; ++s) {
        float* p0 = g_h + rowbase + colbase + s * 8;
        *(float2*)p0 = make_float2(acc[s][0], acc[s][1]);
        *(float2*)(p0 + (size_t)8 * TWO_I) = make_float2(acc[s][2], acc[s][3]);
    }
}

// ---------------- SwiGLU + hi/lo split ---------------------------------------
__global__ void k_act() {
    int ic = blockIdx.x, mt = blockIdx.y, e = blockIdx.z;
    if (mt * 64 >= g_cnt[e]) return;
    int tid = threadIdx.x;
    int c4 = (tid & 31) * 4;   // 0..124
    int r0 = tid >> 5;         // 0..7
#pragma unroll
    for (int rr = 0; rr < 64; rr += 8) {
        int row = mt * 64 + rr + r0;
        size_t hbase = (size_t)(e * T_ + row) * TWO_I + (size_t)ic * 128 + c4;
        float4 g = *(const float4*)(g_h + hbase);
        float4 u = *(const float4*)(g_h + hbase + I_);
        float a0 = u.x * (g.x / (1.f + __expf(-g.x)));
        float a1 = u.y * (g.y / (1.f + __expf(-g.y)));
        float a2 = u.z * (g.z / (1.f + __expf(-g.z)));
        float a3 = u.w * (g.w / (1.f + __expf(-g.w)));
        uint2 uh;
        uh.x = pk2(a0, a1);
        uh.y = pk2(a2, a3);
        __nv_bfloat162 h01 = *reinterpret_cast<__nv_bfloat162*>(&uh.x);
        __nv_bfloat162 h23 = *reinterpret_cast<__nv_bfloat162*>(&uh.y);
        float l0 = a0 - __bfloat162float(h01.x);
        float l1 = a1 - __bfloat162float(h01.y);
        float l2 = a2 - __bfloat162float(h23.x);
        float l3 = a3 - __bfloat162float(h23.y);
        uint2 ul;
        ul.x = pk2(l0, l1);
        ul.y = pk2(l2, l3);
        size_t abase = (size_t)(e * T_ + row) * I_ + (size_t)ic * 128 + c4;
        *(uint2*)(g_ah + abase) = uh;
        *(uint2*)(g_al + abase) = ul;
    }
}

// ---------------- GEMM2: out[tok] += coef * act @ W2^T (block-scaled) --------
__global__ __launch_bounds__(256, 2)
void k_gemm2(const float* __restrict__ w2, const float* __restrict__ w2s,
             float* __restrict__ out) {
    int nt = blockIdx.x, mt = blockIdx.y, e = blockIdx.z;
    int cnt = g_cnt[e];
    if (mt * 64 >= cnt) return;

    __shared__ __align__(16) __nv_bfloat16 sAh[64 * 64];
    __shared__ __align__(16) __nv_bfloat16 sAl[64 * 64];
    __shared__ __align__(16) __nv_bfloat16 sB[128 * 64];

    int tid = threadIdx.x, lane = tid & 31, warp = tid >> 5;
    int wm = warp >> 1, wn = warp & 1;

    int ar = tid >> 2, aq = tid & 3;
    int br = tid >> 1, bh = tid & 1;
    const __nv_bfloat16* ah_row = g_ah + (size_t)(e * T_ + mt * 64 + ar) * I_;
    const __nv_bfloat16* al_row = g_al + (size_t)(e * T_ + mt * 64 + ar) * I_;
    const float* brow = w2 + ((size_t)e * H_ + (size_t)nt * 128 + br) * I_;

    float acc[8][4], tmp[8][4];
#pragma unroll
    for (int s = 0; s < 8; ++s)
#pragma unroll
        for (int j = 0; j < 4; ++j) acc[s][j] = 0.f;

    const int NC = I_ / 64;  // 44
    for (int kc = 0; kc < NC; ++kc) {
        int k0 = kc * 64;
        __syncthreads();
#pragma unroll
        for (int cc = 0; cc < 2; ++cc) {
            int chunk = aq * 2 + cc;
            uint4 vh = *(const uint4*)(ah_row + k0 + chunk * 8);
            uint4 vl = *(const uint4*)(al_row + k0 + chunk * 8);
            *(uint4*)(sAh + swz(ar, chunk)) = vh;
            *(uint4*)(sAl + swz(ar, chunk)) = vl;
        }
#pragma unroll
        for (int cc = 0; cc < 4; ++cc) {
            int chunk = bh * 4 + cc;
            const float* p = brow + k0 + chunk * 8;
            float4 f0 = *(const float4*)p;
            float4 f1 = *(const float4*)(p + 4);
            uint4 u;
            u.x = pk2(f0.x, f0.y); u.y = pk2(f0.z, f0.w);
            u.z = pk2(f1.x, f1.y); u.w = pk2(f1.z, f1.w);
            *(uint4*)(sB + swz(br, chunk)) = u;
        }
        __syncthreads();

        if ((kc & 1) == 0) {
#pragma unroll
            for (int s = 0; s < 8; ++s)
#pragma unroll
                for (int j = 0; j < 4; ++j) tmp[s][j] = 0.f;
        }
#pragma unroll
        for (int ks = 0; ks < 4; ++ks) {
            unsigned ah0, ah1, ah2, ah3, al0, al1, al2, al3;
            {
                int row = wm * 16 + (lane & 15);
                int chunk = ks * 2 + (lane >> 4);
                ldsm4(ah0, ah1, ah2, ah3, sAh + swz(row, chunk));
                ldsm4(al0, al1, al2, al3, sAl + swz(row, chunk));
            }
            unsigned bb[16];
#pragma unroll
            for (int g = 0; g < 4; ++g) {
                int row = wn * 64 + g * 16 + (lane & 7) + ((lane >> 4) << 3);
                int chunk = ks * 2 + ((lane >> 3) & 1);
                ldsm4(bb[4 * g], bb[4 * g + 1], bb[4 * g + 2], bb[4 * g + 3],
                      sB + swz(row, chunk));
            }
#pragma unroll
            for (int s = 0; s < 8; ++s) {
                unsigned b0 = bb[4 * (s >> 1) + 2 * (s & 1)];
                unsigned b1 = bb[4 * (s >> 1) + 2 * (s & 1) + 1];
                mma16816(tmp[s], ah0, ah1, ah2, ah3, b0, b1);
                mma16816(tmp[s], al0, al1, al2, al3, b0, b1);
            }
        }
        if (kc & 1) {
            float sc = w2s[((size_t)e * NB2 + nt) * KB2 + (kc >> 1)];
#pragma unroll
            for (int s = 0; s < 8; ++s)
#pragma unroll
                for (int j = 0; j < 4; ++j) acc[s][j] += sc * tmp[s][j];
        }
    }

    // epilogue: weighted scatter-add into out (<=2 adds/element -> deterministic)
    int r0 = lane >> 2, cb = (lane & 3) * 2;
    int rloc0 = mt * 64 + wm * 16 + r0;
#pragma unroll
    for (int hrow = 0; hrow < 2; ++hrow) {
        int rl = rloc0 + hrow * 8;
        if (rl < cnt) {
            float cf = g_coef[e * T_ + rl];
            if (cf != 0.f) {
                int tok = g_tok[e * T_ + rl];
                float* op = out + (size_t)tok * H_ + nt * 128 + wn * 64 + cb;
#pragma unroll
                for (int s = 0; s < 8; ++s) {
                    atomicAdd(op + s * 8,     cf * acc[s][2 * hrow + 0]);
                    atomicAdd(op + s * 8 + 1, cf * acc[s][2 * hrow + 1]);
                }
            }
        }
    }
}

// ---------------- launcher ---------------------------------------------------
extern "C" void kernel_launch(void* const* d_in, const int* in_sizes, int n_in,
                              void* d_out, int out_size) {
    const float* x    = (const float*)d_in[0];
    const void*  ids  = d_in[1];
    const float* tw   = (const float*)d_in[2];
    const float* w13  = (const float*)d_in[3];
    const float* w13s = (const float*)d_in[4];
    const float* w2   = (const float*)d_in[5];
    const float* w2s  = (const float*)d_in[6];
    float* out = (float*)d_out;

    k_prep<<<(T_ * H_) / 256, 256>>>(x, out);
    k_route<<<1, 256>>>(ids, tw);
    dim3 g1(NB1, 8, E_);
    k_gemm1<<<g1, 256>>>(w13, w13s);
    dim3 ga(KB2, 8, E_);
    k_act<<<ga, 256>>>();
    dim3 g2(NB2, 8, E_);
    k_gemm2<<<g2, 256>>>(w2, w2s, out);
}

// round 15
// speedup vs baseline: 1.0036x; 1.0005x over previous
#include <cuda_runtime.h>
#include <cuda_bf16.h>
#include <cstdint>
#include <cstddef>

// Problem constants
#define E_    8
#define H_    2048
#define I_    2816
#define T_    512
#define TWO_I 5632
#define NB1   44   // (2I)/128 n-blocks for w13_scale
#define KB1   16   // H/128 k-blocks for w13_scale
#define NB2   16   // H/128 n-blocks for w2_scale
#define KB2   22   // I/128 k-blocks for w2_scale

// ---------------- device scratch (no runtime allocation allowed) -------------
__device__ __nv_bfloat16 g_xh[T_ * H_];
__device__ __nv_bfloat16 g_xl[T_ * H_];
__device__ float         g_h[(size_t)E_ * T_ * TWO_I];   // GEMM1 output (fp32)
__device__ __nv_bfloat16 g_ah[(size_t)E_ * T_ * I_];     // act hi
__device__ __nv_bfloat16 g_al[(size_t)E_ * T_ * I_];     // act lo
__device__ int           g_tok[E_ * T_];
__device__ float         g_coef[E_ * T_];
__device__ int           g_cnt[E_];

// ---------------- helpers ----------------------------------------------------
__device__ __forceinline__ unsigned pk2(float a, float b) {
    __nv_bfloat162 t = __floats2bfloat162_rn(a, b);  // a -> low, b -> high
    return *reinterpret_cast<unsigned*>(&t);
}

__device__ __forceinline__ void ldsm4(unsigned& r0, unsigned& r1, unsigned& r2,
                                      unsigned& r3, const void* p) {
    unsigned a = (unsigned)__cvta_generic_to_shared(p);
    asm volatile("ldmatrix.sync.aligned.m8n8.x4.shared.b16 {%0,%1,%2,%3}, [%4];\n"
                 : "=r"(r0), "=r"(r1), "=r"(r2), "=r"(r3)
                 : "r"(a));
}

__device__ __forceinline__ void mma16816(float* c, unsigned a0, unsigned a1,
                                         unsigned a2, unsigned a3,
                                         unsigned b0, unsigned b1) {
    asm volatile(
        "mma.sync.aligned.m16n8k16.row.col.f32.bf16.bf16.f32 "
        "{%0,%1,%2,%3}, {%4,%5,%6,%7}, {%8,%9}, {%0,%1,%2,%3};\n"
        : "+f"(c[0]), "+f"(c[1]), "+f"(c[2]), "+f"(c[3])
        : "r"(a0), "r"(a1), "r"(a2), "r"(a3), "r"(b0), "r"(b1));
}

// Smem swizzle: rows are 64 bf16 (128B) wide; 8 chunks of 8 bf16 (16B).
// chunk' = chunk ^ (row&7) -> conflict-free ldmatrix across 8 rows.
__device__ __forceinline__ int swz(int row, int chunk) {
    return row * 64 + ((chunk ^ (row & 7)) << 3);
}

// ---------------- prep: split x into bf16 hi/lo, zero the output -------------
__global__ void k_prep(const float* __restrict__ x, float* __restrict__ out) {
    int i = blockIdx.x * 256 + threadIdx.x;   // grid sized exactly T_*H_/256
    float v = x[i];
    __nv_bfloat16 h = __float2bfloat16(v);
    g_xh[i] = h;
    g_xl[i] = __float2bfloat16(v - __bfloat162float(h));
    out[i] = 0.f;
}

// ---------------- routing: per-expert token list + coef ---------------------
// topk_ids may be int64 or int32 depending on jax x64 config; detect at runtime.
__global__ void k_route(const void* __restrict__ ids_raw,
                        const float* __restrict__ w) {
    __shared__ int s64;
    int tid = threadIdx.x;
    if (tid == 0) s64 = 1;
    __syncthreads();
    const long long* p64 = (const long long*)ids_raw;
    const int*       p32 = (const int*)ids_raw;
    // First 512 int64 reads = 4096 bytes, in-bounds under both dtypes.
    for (int i = tid; i < 512; i += 256) {
        long long v = p64[i];
        if (v < 0 || v >= E_) s64 = 0;
    }
    __syncthreads();
    int is64 = s64;

    int warp = tid >> 5, lane = tid & 31;
    int e = warp;             // 8 warps, one expert each
    int c = 0;
    for (int t0 = 0; t0 < T_; t0 += 32) {
        int t = t0 + lane;
        int id0, id1;
        if (is64) { id0 = (int)p64[2 * t]; id1 = (int)p64[2 * t + 1]; }
        else      { id0 = p32[2 * t];      id1 = p32[2 * t + 1]; }
        float cf = 0.f;
        bool hit = false;
        if (id0 == e) { cf += w[2 * t];     hit = true; }
        if (id1 == e) { cf += w[2 * t + 1]; hit = true; }
        unsigned m = __ballot_sync(0xffffffffu, hit);
        if (hit) {
            int pos = c + __popc(m & ((1u << lane) - 1u));
            g_tok[e * T_ + pos]  = t;
            g_coef[e * T_ + pos] = cf;
        }
        c += __popc(m);
    }
    if (lane == 0) g_cnt[e] = c;
}

// ---------------- GEMM1: h[slot, n] = sum_k x[tok,k]*W13[e,n,k]*scale -------
// Tile: BM=64 (gathered token rows) x BN=128 x KC=64, 8 warps (4x2),
// warp tile 16x64. A split hi/lo (2 mma passes), scale applied on fp32
// accumulator every 2 k-chunks (= one 128 scale block).
__global__ __launch_bounds__(256, 2)
void k_gemm1(const float* __restrict__ w13, const float* __restrict__ w13s) {
    int nt = blockIdx.x, mt = blockIdx.y, e = blockIdx.z;
    int cnt = g_cnt[e];
    if (mt * 64 >= cnt) return;

    __shared__ __align__(16) __nv_bfloat16 sAh[64 * 64];
    __shared__ __align__(16) __nv_bfloat16 sAl[64 * 64];
    __shared__ __align__(16) __nv_bfloat16 sB[128 * 64];

    int tid = threadIdx.x, lane = tid & 31, warp = tid >> 5;
    int wm = warp >> 1, wn = warp & 1;

    // loader mappings
    int ar = tid >> 2, aq = tid & 3;   // A: 64 rows, 2 chunks/thread
    int br = tid >> 1, bh = tid & 1;   // B: 128 rows, 4 chunks/thread
    int mrow = mt * 64 + ar;
    int tok = (mrow < cnt) ? g_tok[e * T_ + mrow] : -1;
    const __nv_bfloat16* xh_row = g_xh + (size_t)(tok < 0 ? 0 : tok) * H_;
    const __nv_bfloat16* xl_row = g_xl + (size_t)(tok < 0 ? 0 : tok) * H_;
    const float* brow = w13 + ((size_t)e * TWO_I + (size_t)nt * 128 + br) * H_;

    float acc[8][4], tmp[8][4];
#pragma unroll
    for (int s = 0; s < 8; ++s)
#pragma unroll
        for (int j = 0; j < 4; ++j) acc[s][j] = 0.f;

    const int NC = H_ / 64;  // 32
    for (int kc = 0; kc < NC; ++kc) {
        int k0 = kc * 64;
        __syncthreads();
        // --- load A (gathered token rows, already bf16) ---
#pragma unroll
        for (int cc = 0; cc < 2; ++cc) {
            int chunk = aq * 2 + cc;
            uint4 vh = make_uint4(0, 0, 0, 0), vl = make_uint4(0, 0, 0, 0);
            if (tok >= 0) {
                vh = *(const uint4*)(xh_row + k0 + chunk * 8);
                vl = *(const uint4*)(xl_row + k0 + chunk * 8);
            }
            *(uint4*)(sAh + swz(ar, chunk)) = vh;
            *(uint4*)(sAl + swz(ar, chunk)) = vl;
        }
        // --- load B (fp32 -> bf16 exact convert) ---
#pragma unroll
        for (int cc = 0; cc < 4; ++cc) {
            int chunk = bh * 4 + cc;
            const float* p = brow + k0 + chunk * 8;
            float4 f0 = *(const float4*)p;
            float4 f1 = *(const float4*)(p + 4);
            uint4 u;
            u.x = pk2(f0.x, f0.y); u.y = pk2(f0.z, f0.w);
            u.z = pk2(f1.x, f1.y); u.w = pk2(f1.z, f1.w);
            *(uint4*)(sB + swz(br, chunk)) = u;
        }
        __syncthreads();

        if ((kc & 1) == 0) {
#pragma unroll
            for (int s = 0; s < 8; ++s)
#pragma unroll
                for (int j = 0; j < 4; ++j) tmp[s][j] = 0.f;
        }
#pragma unroll
        for (int ks = 0; ks < 4; ++ks) {
            unsigned ah0, ah1, ah2, ah3, al0, al1, al2, al3;
            {
                int row = wm * 16 + (lane & 15);
                int chunk = ks * 2 + (lane >> 4);
                ldsm4(ah0, ah1, ah2, ah3, sAh + swz(row, chunk));
                ldsm4(al0, al1, al2, al3, sAl + swz(row, chunk));
            }
            unsigned bb[16];
#pragma unroll
            for (int g = 0; g < 4; ++g) {
                int row = wn * 64 + g * 16 + (lane & 7) + ((lane >> 4) << 3);
                int chunk = ks * 2 + ((lane >> 3) & 1);
                ldsm4(bb[4 * g], bb[4 * g + 1], bb[4 * g + 2], bb[4 * g + 3],
                      sB + swz(row, chunk));
            }
#pragma unroll
            for (int s = 0; s < 8; ++s) {
                unsigned b0 = bb[4 * (s >> 1) + 2 * (s & 1)];
                unsigned b1 = bb[4 * (s >> 1) + 2 * (s & 1) + 1];
                mma16816(tmp[s], ah0, ah1, ah2, ah3, b0, b1);
                mma16816(tmp[s], al0, al1, al2, al3, b0, b1);
            }
        }
        if (kc & 1) {
            float sc = w13s[((size_t)e * NB1 + nt) * KB1 + (kc >> 1)];
#pragma unroll
            for (int s = 0; s < 8; ++s)
#pragma unroll
                for (int j = 0; j < 4; ++j) acc[s][j] += sc * tmp[s][j];
        }
    }

    // epilogue: write fp32 h tile
    int r0 = lane >> 2, cb = (lane & 3) * 2;
    size_t rowbase = (size_t)(e * T_ + mt * 64 + wm * 16 + r0) * TWO_I;
    int colbase = nt * 128 + wn * 64 + cb;
#pragma unroll
    for (int s = 0; s < 8; ++s) {
        float* p0 = g_h + rowbase + colbase + s * 8;
        *(float2*)p0 = make_float2(acc[s][0], acc[s][1]);
        *(float2*)(p0 + (size_t)8 * TWO_I) = make_float2(acc[s][2], acc[s][3]);
    }
}

// ---------------- SwiGLU + hi/lo split ---------------------------------------
__global__ void k_act() {
    int ic = blockIdx.x, mt = blockIdx.y, e = blockIdx.z;
    if (mt * 64 >= g_cnt[e]) return;
    int tid = threadIdx.x;
    int c4 = (tid & 31) * 4;   // 0..124
    int r0 = tid >> 5;         // 0..7
#pragma unroll
    for (int rr = 0; rr < 64; rr += 8) {
        int row = mt * 64 + rr + r0;
        size_t hbase = (size_t)(e * T_ + row) * TWO_I + (size_t)ic * 128 + c4;
        float4 g = *(const float4*)(g_h + hbase);
        float4 u = *(const float4*)(g_h + hbase + I_);
        float a0 = u.x * (g.x / (1.f + __expf(-g.x)));
        float a1 = u.y * (g.y / (1.f + __expf(-g.y)));
        float a2 = u.z * (g.z / (1.f + __expf(-g.z)));
        float a3 = u.w * (g.w / (1.f + __expf(-g.w)));
        uint2 uh;
        uh.x = pk2(a0, a1);
        uh.y = pk2(a2, a3);
        __nv_bfloat162 h01 = *reinterpret_cast<__nv_bfloat162*>(&uh.x);
        __nv_bfloat162 h23 = *reinterpret_cast<__nv_bfloat162*>(&uh.y);
        float l0 = a0 - __bfloat162float(h01.x);
        float l1 = a1 - __bfloat162float(h01.y);
        float l2 = a2 - __bfloat162float(h23.x);
        float l3 = a3 - __bfloat162float(h23.y);
        uint2 ul;
        ul.x = pk2(l0, l1);
        ul.y = pk2(l2, l3);
        size_t abase = (size_t)(e * T_ + row) * I_ + (size_t)ic * 128 + c4;
        *(uint2*)(g_ah + abase) = uh;
        *(uint2*)(g_al + abase) = ul;
    }
}

// ---------------- GEMM2: out[tok] += coef * act @ W2^T (block-scaled) --------
__global__ __launch_bounds__(256, 2)
void k_gemm2(const float* __restrict__ w2, const float* __restrict__ w2s,
             float* __restrict__ out) {
    int nt = blockIdx.x, mt = blockIdx.y, e = blockIdx.z;
    int cnt = g_cnt[e];
    if (mt * 64 >= cnt) return;

    __shared__ __align__(16) __nv_bfloat16 sAh[64 * 64];
    __shared__ __align__(16) __nv_bfloat16 sAl[64 * 64];
    __shared__ __align__(16) __nv_bfloat16 sB[128 * 64];

    int tid = threadIdx.x, lane = tid & 31, warp = tid >> 5;
    int wm = warp >> 1, wn = warp & 1;

    int ar = tid >> 2, aq = tid & 3;
    int br = tid >> 1, bh = tid & 1;
    const __nv_bfloat16* ah_row = g_ah + (size_t)(e * T_ + mt * 64 + ar) * I_;
    const __nv_bfloat16* al_row = g_al + (size_t)(e * T_ + mt * 64 + ar) * I_;
    const float* brow = w2 + ((size_t)e * H_ + (size_t)nt * 128 + br) * I_;

    float acc[8][4], tmp[8][4];
#pragma unroll
    for (int s = 0; s < 8; ++s)
#pragma unroll
        for (int j = 0; j < 4; ++j) acc[s][j] = 0.f;

    const int NC = I_ / 64;  // 44
    for (int kc = 0; kc < NC; ++kc) {
        int k0 = kc * 64;
        __syncthreads();
#pragma unroll
        for (int cc = 0; cc < 2; ++cc) {
            int chunk = aq * 2 + cc;
            uint4 vh = *(const uint4*)(ah_row + k0 + chunk * 8);
            uint4 vl = *(const uint4*)(al_row + k0 + chunk * 8);
            *(uint4*)(sAh + swz(ar, chunk)) = vh;
            *(uint4*)(sAl + swz(ar, chunk)) = vl;
        }
#pragma unroll
        for (int cc = 0; cc < 4; ++cc) {
            int chunk = bh * 4 + cc;
            const float* p = brow + k0 + chunk * 8;
            float4 f0 = *(const float4*)p;
            float4 f1 = *(const float4*)(p + 4);
            uint4 u;
            u.x = pk2(f0.x, f0.y); u.y = pk2(f0.z, f0.w);
            u.z = pk2(f1.x, f1.y); u.w = pk2(f1.z, f1.w);
            *(uint4*)(sB + swz(br, chunk)) = u;
        }
        __syncthreads();

        if ((kc & 1) == 0) {
#pragma unroll
            for (int s = 0; s < 8; ++s)
#pragma unroll
                for (int j = 0; j < 4; ++j) tmp[s][j] = 0.f;
        }
#pragma unroll
        for (int ks = 0; ks < 4; ++ks) {
            unsigned ah0, ah1, ah2, ah3, al0, al1, al2, al3;
            {
                int row = wm * 16 + (lane & 15);
                int chunk = ks * 2 + (lane >> 4);
                ldsm4(ah0, ah1, ah2, ah3, sAh + swz(row, chunk));
                ldsm4(al0, al1, al2, al3, sAl + swz(row, chunk));
            }
            unsigned bb[16];
#pragma unroll
            for (int g = 0; g < 4; ++g) {
                int row = wn * 64 + g * 16 + (lane & 7) + ((lane >> 4) << 3);
                int chunk = ks * 2 + ((lane >> 3) & 1);
                ldsm4(bb[4 * g], bb[4 * g + 1], bb[4 * g + 2], bb[4 * g + 3],
                      sB + swz(row, chunk));
            }
#pragma unroll
            for (int s = 0; s < 8; ++s) {
                unsigned b0 = bb[4 * (s >> 1) + 2 * (s & 1)];
                unsigned b1 = bb[4 * (s >> 1) + 2 * (s & 1) + 1];
                mma16816(tmp[s], ah0, ah1, ah2, ah3, b0, b1);
                mma16816(tmp[s], al0, al1, al2, al3, b0, b1);
            }
        }
        if (kc & 1) {
            float sc = w2s[((size_t)e * NB2 + nt) * KB2 + (kc >> 1)];
#pragma unroll
            for (int s = 0; s < 8; ++s)
#pragma unroll
                for (int j = 0; j < 4; ++j) acc[s][j] += sc * tmp[s][j];
        }
    }

    // epilogue: weighted scatter-add into out (<=2 adds/element -> deterministic)
    int r0 = lane >> 2, cb = (lane & 3) * 2;
    int rloc0 = mt * 64 + wm * 16 + r0;
#pragma unroll
    for (int hrow = 0; hrow < 2; ++hrow) {
        int rl = rloc0 + hrow * 8;
        if (rl < cnt) {
            float cf = g_coef[e * T_ + rl];
            if (cf != 0.f) {
                int tok = g_tok[e * T_ + rl];
                float* op = out + (size_t)tok * H_ + nt * 128 + wn * 64 + cb;
#pragma unroll
                for (int s = 0; s < 8; ++s) {
                    atomicAdd(op + s * 8,     cf * acc[s][2 * hrow + 0]);
                    atomicAdd(op + s * 8 + 1, cf * acc[s][2 * hrow + 1]);
                }
            }
        }
    }
}

// ---------------- launcher ---------------------------------------------------
extern "C" void kernel_launch(void* const* d_in, const int* in_sizes, int n_in,
                              void* d_out, int out_size) {
    const float* x    = (const float*)d_in[0];
    const void*  ids  = d_in[1];
    const float* tw   = (const float*)d_in[2];
    const float* w13  = (const float*)d_in[3];
    const float* w13s = (const float*)d_in[4];
    const float* w2   = (const float*)d_in[5];
    const float* w2s  = (const float*)d_in[6];
    float* out = (float*)d_out;

    k_prep<<<(T_ * H_) / 256, 256>>>(x, out);
    k_route<<<1, 256>>>(ids, tw);
    dim3 g1(NB1, 8, E_);
    k_gemm1<<<g1, 256>>>(w13, w13s);
    dim3 ga(KB2, 8, E_);
    k_act<<<ga, 256>>>();
    dim3 g2(NB2, 8, E_);
    k_gemm2<<<g2, 256>>>(w2, w2s, out);
}